// round 15
// baseline (speedup 1.0000x reference)
#include <cuda_runtime.h>
#include <cuda_bf16.h>
#include <mma.h>

using namespace nvcuda;

#define MAXN 50000
#define MAXE 1000000
#define MT   391          // ceil(50000/128) m-tiles

typedef unsigned int u32;

// ---------------- scratch (device globals, no allocation) -------------------
__device__ __align__(16) float g_dinv[MAXN];
__device__ __align__(16) float g_buf2[MAXN * 128];   // T2
__device__ __align__(16) int g_cnt[MAXN];
__device__ int g_off[MAXN];
__device__ int g_pos[MAXN];
__device__ int g_srt[MAXE];
// pre-split bf16 weights (row-major)
__device__ __align__(16) __nv_bfloat16 g_w1hi[128 * 512], g_w1lo[128 * 512];
__device__ __align__(16) __nv_bfloat16 g_w3hi[512 * 128], g_w3lo[512 * 128];
__device__ __align__(16) __nv_bfloat16 g_fc1hi[256 * 128], g_fc1lo[256 * 128];

// ---------------- helpers -----------------------------------------------------
__device__ __forceinline__ float leaky(float v) { return v >= 0.f ? v : 0.01f * v; }

__device__ __forceinline__ unsigned short f2bf(float v) {
    __nv_bfloat16 h = __float2bfloat16_rn(v);
    return static_cast<__nv_bfloat16_raw>(h).x;
}
__device__ __forceinline__ float bf2f(unsigned short u) {
    __nv_bfloat16_raw r; r.x = u;
    return __bfloat162float(__nv_bfloat16(r));
}
__device__ __forceinline__ void bsplit(float v, unsigned short& h, unsigned short& l) {
    h = f2bf(v);
    l = f2bf(v - bf2f(h));
}

// smem strides (padded to rotate banks; keep 16B alignment)
#define SB 136            // bf16 elements per row  (272 B = 17*16)
#define SF 132            // fp32 elements per row  (528 B = 33*16)
#define O_AHI 0
#define O_ALO (128 * SB)
#define O_BHI (2 * 128 * SB)
#define O_BLO (3 * 128 * SB)
#define O_HHI (4 * 128 * SB)
#define O_HLO (5 * 128 * SB)
#define WG_TOTAL_BYTES (6 * 128 * SB * 2)   // 208896

#define HF 264
#define HS_TOTAL_BYTES 69632

// ---------------- CSR build: hist + weight-prep merged -------------------------
__global__ void k_histprep(const int* __restrict__ ei, int E,
                           const float* __restrict__ W1,
                           const float* __restrict__ W3,
                           const float* __restrict__ fc1w) {
    int i = blockIdx.x * blockDim.x + threadIdx.x;

    // weight split (independent work, rides along)
    if (i < 163840) {
        unsigned short h, l;
        if (i < 65536) {
            bsplit(W1[i], h, l);
            ((unsigned short*)g_w1hi)[i] = h;
            ((unsigned short*)g_w1lo)[i] = l;
        } else if (i < 131072) {
            int j = i - 65536;
            bsplit(W3[j], h, l);
            ((unsigned short*)g_w3hi)[j] = h;
            ((unsigned short*)g_w3lo)[j] = l;
        } else {
            int j = i - 131072;
            bsplit(fc1w[j], h, l);
            ((unsigned short*)g_fc1hi)[j] = h;
            ((unsigned short*)g_fc1lo)[j] = l;
        }
    }

    // degree histogram (4 edges/thread)
    int b = i * 4;
    if (b + 3 < E) {
        int4 d = *reinterpret_cast<const int4*>(ei + E + b);
        atomicAdd(&g_cnt[d.x], 1);
        atomicAdd(&g_cnt[d.y], 1);
        atomicAdd(&g_cnt[d.z], 1);
        atomicAdd(&g_cnt[d.w], 1);
    } else {
        for (int j = b; j < E; j++) atomicAdd(&g_cnt[ei[E + j]], 1);
    }
}

__global__ void __launch_bounds__(1024) k_scan(int n) {
    __shared__ int tmp[1024];
    int tid = threadIdx.x;
    int chunk = (n + 1023) >> 10;
    chunk = (chunk + 3) & ~3;                 // multiple of 4 for int4 loads
    int start = tid * chunk;
    int end = start + chunk; if (end > n) end = n;

    int s = 0;
    int i = start;
    for (; i + 3 < end; i += 4) {
        int4 v = *reinterpret_cast<const int4*>(g_cnt + i);
        s += v.x + v.y + v.z + v.w;
    }
    for (; i < end; i++) s += g_cnt[i];
    tmp[tid] = s;
    __syncthreads();
    for (int off = 1; off < 1024; off <<= 1) {
        int v = (tid >= off) ? tmp[tid - off] : 0;
        __syncthreads();
        tmp[tid] += v;
        __syncthreads();
    }
    int base = tmp[tid] - s;  // exclusive prefix
    i = start;
    for (; i + 3 < end; i += 4) {
        int4 v = *reinterpret_cast<const int4*>(g_cnt + i);
        int c0 = v.x, c1 = v.y, c2 = v.z, c3 = v.w;
        g_off[i] = base;     g_pos[i] = base;     g_dinv[i] = rsqrtf((float)(c0 + 1));     base += c0;
        g_off[i + 1] = base; g_pos[i + 1] = base; g_dinv[i + 1] = rsqrtf((float)(c1 + 1)); base += c1;
        g_off[i + 2] = base; g_pos[i + 2] = base; g_dinv[i + 2] = rsqrtf((float)(c2 + 1)); base += c2;
        g_off[i + 3] = base; g_pos[i + 3] = base; g_dinv[i + 3] = rsqrtf((float)(c3 + 1)); base += c3;
    }
    for (; i < end; i++) {
        int c = g_cnt[i];
        g_off[i] = base; g_pos[i] = base;
        g_dinv[i] = rsqrtf((float)(c + 1));
        base += c;
    }
}
__global__ void k_scatter(const int* __restrict__ ei, int E) {
    int i = blockIdx.x * blockDim.x + threadIdx.x;
    int b = i * 4;
    if (b + 3 < E) {
        int4 s = *reinterpret_cast<const int4*>(ei + b);
        int4 d = *reinterpret_cast<const int4*>(ei + E + b);
        g_srt[atomicAdd(&g_pos[d.x], 1)] = s.x;
        g_srt[atomicAdd(&g_pos[d.y], 1)] = s.y;
        g_srt[atomicAdd(&g_pos[d.z], 1)] = s.z;
        g_srt[atomicAdd(&g_pos[d.w], 1)] = s.w;
    } else {
        for (int j = b; j < E; j++)
            g_srt[atomicAdd(&g_pos[ei[E + j]], 1)] = ei[j];
    }
}

// ---------------- CSR pull of one node's features (8-edge unroll) --------------
__device__ __forceinline__ float4 pull_node(const float* __restrict__ in,
                                            int node, int lane) {
    int off = g_off[node], cnt = g_cnt[node];
    float dd = g_dinv[node];
    float4 v = reinterpret_cast<const float4*>(in + (size_t)node * 128)[lane];
    float4 acc;
    acc.x = dd * v.x; acc.y = dd * v.y; acc.z = dd * v.z; acc.w = dd * v.w;
    int j = 0;
    for (; j + 7 < cnt; j += 8) {
        int s0 = g_srt[off + j],     s1 = g_srt[off + j + 1];
        int s2 = g_srt[off + j + 2], s3 = g_srt[off + j + 3];
        int s4 = g_srt[off + j + 4], s5 = g_srt[off + j + 5];
        int s6 = g_srt[off + j + 6], s7 = g_srt[off + j + 7];
        float w0 = g_dinv[s0], w1 = g_dinv[s1], w2 = g_dinv[s2], w3 = g_dinv[s3];
        float w4 = g_dinv[s4], w5 = g_dinv[s5], w6 = g_dinv[s6], w7 = g_dinv[s7];
        float4 a0 = reinterpret_cast<const float4*>(in + (size_t)s0 * 128)[lane];
        float4 a1 = reinterpret_cast<const float4*>(in + (size_t)s1 * 128)[lane];
        float4 a2 = reinterpret_cast<const float4*>(in + (size_t)s2 * 128)[lane];
        float4 a3 = reinterpret_cast<const float4*>(in + (size_t)s3 * 128)[lane];
        float4 a4 = reinterpret_cast<const float4*>(in + (size_t)s4 * 128)[lane];
        float4 a5 = reinterpret_cast<const float4*>(in + (size_t)s5 * 128)[lane];
        float4 a6 = reinterpret_cast<const float4*>(in + (size_t)s6 * 128)[lane];
        float4 a7 = reinterpret_cast<const float4*>(in + (size_t)s7 * 128)[lane];
        acc.x += w0 * a0.x + w1 * a1.x + w2 * a2.x + w3 * a3.x
               + w4 * a4.x + w5 * a5.x + w6 * a6.x + w7 * a7.x;
        acc.y += w0 * a0.y + w1 * a1.y + w2 * a2.y + w3 * a3.y
               + w4 * a4.y + w5 * a5.y + w6 * a6.y + w7 * a7.y;
        acc.z += w0 * a0.z + w1 * a1.z + w2 * a2.z + w3 * a3.z
               + w4 * a4.z + w5 * a5.z + w6 * a6.z + w7 * a7.z;
        acc.w += w0 * a0.w + w1 * a1.w + w2 * a2.w + w3 * a3.w
               + w4 * a4.w + w5 * a5.w + w6 * a6.w + w7 * a7.w;
    }
    for (; j < cnt; j++) {
        int s0 = g_srt[off + j];
        float w0 = g_dinv[s0];
        float4 a = reinterpret_cast<const float4*>(in + (size_t)s0 * 128)[lane];
        acc.x += w0 * a.x; acc.y += w0 * a.y; acc.z += w0 * a.z; acc.w += w0 * a.w;
    }
    acc.x *= dd; acc.y *= dd; acc.z *= dd; acc.w *= dd;
    return acc;
}

// ---------------- fused: pull1 + GEMM pair  T2 = leaky(Ahat@x@W1+b1)@W3 --------
// grid (MT); block 256 = 8 warps (4m x 2n). Phase A: warp gathers 16 nodes from
// x directly into split-bf16 A tile (no g_buf1 round-trip).
__global__ void __launch_bounds__(256) k_wgemm12(const float* __restrict__ x,
                                                 const float* __restrict__ b1,
                                                 int n) {
    extern __shared__ __nv_bfloat16 sh[];
    __nv_bfloat16* s_ahi = sh + O_AHI;
    __nv_bfloat16* s_alo = sh + O_ALO;
    __nv_bfloat16* s_bhi = sh + O_BHI;
    __nv_bfloat16* s_blo = sh + O_BLO;
    __nv_bfloat16* s_hhi = sh + O_HHI;
    __nv_bfloat16* s_hlo = sh + O_HLO;
    float* stg = reinterpret_cast<float*>(sh + O_BHI);   // fp32 staging [128][SF]

    int tid = threadIdx.x;
    int wid = tid >> 5;
    int lane = tid & 31;
    int base = blockIdx.x * 128;
    int wm = wid & 3;       // rows wm*32
    int wn = wid >> 2;      // cols wn*64

    // Phase A: CSR pull from x -> split bf16 A tile (16 nodes per warp)
    for (int i = 0; i < 16; i++) {
        int r = wid * 16 + i;
        int node = base + r;
        float4 acc = make_float4(0.f, 0.f, 0.f, 0.f);
        if (node < n) acc = pull_node(x, node, lane);
        ushort4 h, l;
        bsplit(acc.x, h.x, l.x); bsplit(acc.y, h.y, l.y);
        bsplit(acc.z, h.z, l.z); bsplit(acc.w, h.w, l.w);
        *reinterpret_cast<ushort4*>(s_ahi + r * SB + lane * 4) = h;
        *reinterpret_cast<ushort4*>(s_alo + r * SB + lane * 4) = l;
    }

    wmma::fragment<wmma::accumulator, 16, 16, 16, float> acc2[2][4];
#pragma unroll
    for (int mi = 0; mi < 2; mi++)
#pragma unroll
        for (int j = 0; j < 4; j++) wmma::fill_fragment(acc2[mi][j], 0.f);

    for (int c = 0; c < 4; c++) {
        // load W1 slice c (B for mainloop1)
        for (int it = tid; it < 128 * 16; it += 256) {
            int r = it >> 4, c8 = (it & 15) << 3;
            *reinterpret_cast<uint4*>(s_bhi + r * SB + c8) =
                *reinterpret_cast<const uint4*>(g_w1hi + r * 512 + c * 128 + c8);
            *reinterpret_cast<uint4*>(s_blo + r * SB + c8) =
                *reinterpret_cast<const uint4*>(g_w1lo + r * 512 + c * 128 + c8);
        }
        __syncthreads();

        // mainloop1: acc1 = A1 @ W1slice
        wmma::fragment<wmma::accumulator, 16, 16, 16, float> acc1[2][4];
#pragma unroll
        for (int mi = 0; mi < 2; mi++)
#pragma unroll
            for (int j = 0; j < 4; j++) wmma::fill_fragment(acc1[mi][j], 0.f);

#pragma unroll
        for (int ks = 0; ks < 8; ks++) {
            wmma::fragment<wmma::matrix_a, 16, 16, 16, __nv_bfloat16, wmma::row_major> ahi[2], alo[2];
#pragma unroll
            for (int mi = 0; mi < 2; mi++) {
                wmma::load_matrix_sync(ahi[mi], s_ahi + (wm * 32 + mi * 16) * SB + ks * 16, SB);
                wmma::load_matrix_sync(alo[mi], s_alo + (wm * 32 + mi * 16) * SB + ks * 16, SB);
            }
#pragma unroll
            for (int j = 0; j < 4; j++) {
                wmma::fragment<wmma::matrix_b, 16, 16, 16, __nv_bfloat16, wmma::row_major> bhi, blo;
                int col = wn * 64 + j * 16;
                wmma::load_matrix_sync(bhi, s_bhi + (ks * 16) * SB + col, SB);
                wmma::load_matrix_sync(blo, s_blo + (ks * 16) * SB + col, SB);
#pragma unroll
                for (int mi = 0; mi < 2; mi++) {
                    wmma::mma_sync(acc1[mi][j], ahi[mi], bhi, acc1[mi][j]);
                    wmma::mma_sync(acc1[mi][j], alo[mi], bhi, acc1[mi][j]);
                    wmma::mma_sync(acc1[mi][j], ahi[mi], blo, acc1[mi][j]);
                }
            }
        }
        __syncthreads();      // all warps done reading s_b -> reuse as staging

        // stage acc1 fp32 into s_b region
#pragma unroll
        for (int mi = 0; mi < 2; mi++)
#pragma unroll
            for (int j = 0; j < 4; j++)
                wmma::store_matrix_sync(stg + (wm * 32 + mi * 16) * SF + wn * 64 + j * 16,
                                        acc1[mi][j], SF, wmma::mem_row_major);
        __syncthreads();

        // bias + leaky + split -> H chunk (s_h)
        for (int it = tid; it < 128 * 32; it += 256) {
            int r = it >> 5, c4 = (it & 31) << 2;
            float4 v = *reinterpret_cast<float4*>(stg + r * SF + c4);
            float4 bb = *reinterpret_cast<const float4*>(b1 + c * 128 + c4);
            v.x = leaky(v.x + bb.x); v.y = leaky(v.y + bb.y);
            v.z = leaky(v.z + bb.z); v.w = leaky(v.w + bb.w);
            ushort4 h, l;
            bsplit(v.x, h.x, l.x); bsplit(v.y, h.y, l.y);
            bsplit(v.z, h.z, l.z); bsplit(v.w, h.w, l.w);
            *reinterpret_cast<ushort4*>(s_hhi + r * SB + c4) = h;
            *reinterpret_cast<ushort4*>(s_hlo + r * SB + c4) = l;
        }
        __syncthreads();

        // load W3 chunk c into s_b (overwrites staging)
        for (int it = tid; it < 128 * 16; it += 256) {
            int r = it >> 4, c8 = (it & 15) << 3;
            *reinterpret_cast<uint4*>(s_bhi + r * SB + c8) =
                *reinterpret_cast<const uint4*>(g_w3hi + (c * 128 + r) * 128 + c8);
            *reinterpret_cast<uint4*>(s_blo + r * SB + c8) =
                *reinterpret_cast<const uint4*>(g_w3lo + (c * 128 + r) * 128 + c8);
        }
        __syncthreads();

        // mainloop2: acc2 += Hchunk @ W3chunk
#pragma unroll
        for (int ks = 0; ks < 8; ks++) {
            wmma::fragment<wmma::matrix_a, 16, 16, 16, __nv_bfloat16, wmma::row_major> ahi[2], alo[2];
#pragma unroll
            for (int mi = 0; mi < 2; mi++) {
                wmma::load_matrix_sync(ahi[mi], s_hhi + (wm * 32 + mi * 16) * SB + ks * 16, SB);
                wmma::load_matrix_sync(alo[mi], s_hlo + (wm * 32 + mi * 16) * SB + ks * 16, SB);
            }
#pragma unroll
            for (int j = 0; j < 4; j++) {
                wmma::fragment<wmma::matrix_b, 16, 16, 16, __nv_bfloat16, wmma::row_major> bhi, blo;
                int col = wn * 64 + j * 16;
                wmma::load_matrix_sync(bhi, s_bhi + (ks * 16) * SB + col, SB);
                wmma::load_matrix_sync(blo, s_blo + (ks * 16) * SB + col, SB);
#pragma unroll
                for (int mi = 0; mi < 2; mi++) {
                    wmma::mma_sync(acc2[mi][j], ahi[mi], bhi, acc2[mi][j]);
                    wmma::mma_sync(acc2[mi][j], alo[mi], bhi, acc2[mi][j]);
                    wmma::mma_sync(acc2[mi][j], ahi[mi], blo, acc2[mi][j]);
                }
            }
        }
        __syncthreads();      // before next chunk reuses s_b / s_h
    }

    // epilogue: T2 -> g_buf2
#pragma unroll
    for (int mi = 0; mi < 2; mi++)
#pragma unroll
        for (int j = 0; j < 4; j++)
            wmma::store_matrix_sync(stg + (wm * 32 + mi * 16) * SF + wn * 64 + j * 16,
                                    acc2[mi][j], SF, wmma::mem_row_major);
    __syncthreads();

    for (int it = tid; it < 128 * 32; it += 256) {
        int r = it >> 5, c4 = (it & 31) << 2;
        if (base + r >= n) continue;
        float4 v = *reinterpret_cast<float4*>(stg + r * SF + c4);
        *reinterpret_cast<float4*>(g_buf2 + (size_t)(base + r) * 128 + c4) = v;
    }
}

// ---------------- fused pull2 + head (R14-proven, untouched) -------------------
__global__ void __launch_bounds__(256) k_pull_final(
    const float* __restrict__ b3, const float* __restrict__ fc1b,
    const float* __restrict__ fc2w, const float* __restrict__ fc2b,
    float* __restrict__ out, int n) {
    extern __shared__ __nv_bfloat16 sh[];
    __nv_bfloat16* s_ahi = sh;
    __nv_bfloat16* s_alo = sh + 64 * SB;

    int tid = threadIdx.x;
    int wid = tid >> 5;
    int lane = tid & 31;
    int base = blockIdx.x * 64;

    float4 bb = reinterpret_cast<const float4*>(b3)[lane];

    for (int i = 0; i < 8; i++) {
        int r = wid * 8 + i;
        int node = base + r;
        float4 acc = make_float4(0.f, 0.f, 0.f, 0.f);
        if (node < n) {
            acc = pull_node(g_buf2, node, lane);
            acc.x = leaky(acc.x + bb.x);
            acc.y = leaky(acc.y + bb.y);
            acc.z = leaky(acc.z + bb.z);
            acc.w = leaky(acc.w + bb.w);
        }
        ushort4 h, l;
        bsplit(acc.x, h.x, l.x); bsplit(acc.y, h.y, l.y);
        bsplit(acc.z, h.z, l.z); bsplit(acc.w, h.w, l.w);
        *reinterpret_cast<ushort4*>(s_ahi + r * SB + lane * 4) = h;
        *reinterpret_cast<ushort4*>(s_alo + r * SB + lane * 4) = l;
    }
    __syncthreads();

    int wm = wid & 1;
    int wn = wid >> 1;
    wmma::fragment<wmma::accumulator, 16, 16, 16, float> acc[2][4];
#pragma unroll
    for (int mi = 0; mi < 2; mi++)
#pragma unroll
        for (int j = 0; j < 4; j++) wmma::fill_fragment(acc[mi][j], 0.f);

#pragma unroll
    for (int ks = 0; ks < 8; ks++) {
        wmma::fragment<wmma::matrix_a, 16, 16, 16, __nv_bfloat16, wmma::row_major> ahi[2], alo[2];
#pragma unroll
        for (int mi = 0; mi < 2; mi++) {
            wmma::load_matrix_sync(ahi[mi], s_ahi + (wm * 32 + mi * 16) * SB + ks * 16, SB);
            wmma::load_matrix_sync(alo[mi], s_alo + (wm * 32 + mi * 16) * SB + ks * 16, SB);
        }
#pragma unroll
        for (int j = 0; j < 4; j++) {
            int col = wn * 64 + j * 16;
            wmma::fragment<wmma::matrix_b, 16, 16, 16, __nv_bfloat16, wmma::col_major> bhi, blo;
            wmma::load_matrix_sync(bhi, g_fc1hi + (size_t)col * 128 + ks * 16, 128);
            wmma::load_matrix_sync(blo, g_fc1lo + (size_t)col * 128 + ks * 16, 128);
#pragma unroll
            for (int mi = 0; mi < 2; mi++) {
                wmma::mma_sync(acc[mi][j], ahi[mi], bhi, acc[mi][j]);
                wmma::mma_sync(acc[mi][j], alo[mi], bhi, acc[mi][j]);
                wmma::mma_sync(acc[mi][j], ahi[mi], blo, acc[mi][j]);
            }
        }
    }
    __syncthreads();

    float* e = reinterpret_cast<float*>(sh);
#pragma unroll
    for (int mi = 0; mi < 2; mi++)
#pragma unroll
        for (int j = 0; j < 4; j++)
            wmma::store_matrix_sync(e + (wm * 32 + mi * 16) * HF + wn * 64 + j * 16,
                                    acc[mi][j], HF, wmma::mem_row_major);
    __syncthreads();

    {
        int node = tid >> 2;
        int part = tid & 3;
        float s = 0.f;
        const float* er = e + node * HF + part * 64;
#pragma unroll
        for (int c4 = 0; c4 < 16; c4++) {
            float4 v = *reinterpret_cast<const float4*>(er + c4 * 4);
            float4 fb = *reinterpret_cast<const float4*>(fc1b + part * 64 + c4 * 4);
            float4 w2 = *reinterpret_cast<const float4*>(fc2w + part * 64 + c4 * 4);
            s += leaky(v.x + fb.x) * w2.x + leaky(v.y + fb.y) * w2.y
               + leaky(v.z + fb.z) * w2.z + leaky(v.w + fb.w) * w2.w;
        }
        s += __shfl_xor_sync(0xffffffffu, s, 1);
        s += __shfl_xor_sync(0xffffffffu, s, 2);
        if (part == 0 && base + node < n)
            out[base + node] = s + fc2b[0];
    }
}

// ---------------------------------------------------------------------------
extern "C" void kernel_launch(void* const* d_in, const int* in_sizes, int n_in,
                              void* d_out, int out_size) {
    const float* x    = (const float*)d_in[0];
    const int*   ei   = (const int*)d_in[1];   // int32 (JAX x64 disabled)
    const float* W1   = (const float*)d_in[2];
    const float* b1   = (const float*)d_in[3];
    const float* W3   = (const float*)d_in[4];
    const float* b3   = (const float*)d_in[5];
    const float* fc1w = (const float*)d_in[6];
    const float* fc1b = (const float*)d_in[7];
    const float* fc2w = (const float*)d_in[8];
    const float* fc2b = (const float*)d_in[9];
    float* out = (float*)d_out;

    int n = in_sizes[0] / 128;
    int E = in_sizes[1] / 2;
    int mt = (n + 127) / 128;
    int mt64 = (n + 63) / 64;

    static int smem_set = 0;
    static void* cnt_ptr = nullptr;
    if (!smem_set) {
        cudaFuncSetAttribute(k_wgemm12, cudaFuncAttributeMaxDynamicSharedMemorySize,
                             WG_TOTAL_BYTES);
        cudaFuncSetAttribute(k_pull_final, cudaFuncAttributeMaxDynamicSharedMemorySize,
                             HS_TOTAL_BYTES);
        cudaGetSymbolAddress(&cnt_ptr, g_cnt);
        smem_set = 1;
    }

    // CSR build (zero via memset node: not a kernel launch)
    cudaMemsetAsync(cnt_ptr, 0, (size_t)n * sizeof(int), 0);
    k_histprep<<<(E / 4 + 255) / 256, 256>>>(ei, E, W1, W3, fc1w);  // launch 0
    k_scan<<<1, 1024>>>(n);                                         // launch 1
    k_scatter<<<(E / 4 + 255) / 256, 256>>>(ei, E);                 // launch 2

    // T2 = leaky((Ahat@x)@W1+b1) @ W3 -> g_buf2   (pull1 fused)   // launch 3 (profiled)
    k_wgemm12<<<mt, 256, WG_TOTAL_BYTES>>>(x, b1, n);
    // out = FC2(leaky(FC1(leaky(Ahat@T2 + b3))))  (pull2 fused)
    k_pull_final<<<mt64, 256, HS_TOTAL_BYTES>>>(b3, fc1b, fc2w, fc2b, out, n);
}

// round 16
// speedup vs baseline: 1.0771x; 1.0771x over previous
#include <cuda_runtime.h>
#include <cuda_bf16.h>
#include <mma.h>

using namespace nvcuda;

#define MAXN 50000
#define MAXE 1000000
#define MT   391          // ceil(50000/128) m-tiles

typedef unsigned int u32;

// ---------------- scratch (device globals, no allocation) -------------------
__device__ __align__(16) float g_dinv[MAXN];
__device__ __align__(16) float g_buf1[MAXN * 128];   // A1, then A2
__device__ __align__(16) float g_buf2[MAXN * 128];   // T2
__device__ __align__(16) int g_cnt[MAXN];
__device__ int g_off[MAXN];
__device__ int g_pos[MAXN];
__device__ int g_srt[MAXE];
// pre-split bf16 weights (row-major)
__device__ __align__(16) __nv_bfloat16 g_w1hi[128 * 512], g_w1lo[128 * 512];
__device__ __align__(16) __nv_bfloat16 g_w3hi[512 * 128], g_w3lo[512 * 128];
__device__ __align__(16) __nv_bfloat16 g_fc1hi[256 * 128], g_fc1lo[256 * 128];

// ---------------- helpers -----------------------------------------------------
__device__ __forceinline__ float leaky(float v) { return v >= 0.f ? v : 0.01f * v; }

__device__ __forceinline__ unsigned short f2bf(float v) {
    __nv_bfloat16 h = __float2bfloat16_rn(v);
    return static_cast<__nv_bfloat16_raw>(h).x;
}
__device__ __forceinline__ float bf2f(unsigned short u) {
    __nv_bfloat16_raw r; r.x = u;
    return __bfloat162float(__nv_bfloat16(r));
}
__device__ __forceinline__ void bsplit(float v, unsigned short& h, unsigned short& l) {
    h = f2bf(v);
    l = f2bf(v - bf2f(h));
}

// smem strides (padded to rotate banks; keep 16B alignment)
#define SB 136            // bf16 elements per row  (272 B = 17*16)
#define SF 132            // fp32 elements per row  (528 B = 33*16)
#define O_AHI 0
#define O_ALO (128 * SB)
#define O_BHI (2 * 128 * SB)
#define O_BLO (3 * 128 * SB)
#define O_HHI (4 * 128 * SB)
#define O_HLO (5 * 128 * SB)
#define WG_TOTAL_BYTES (6 * 128 * SB * 2)   // 208896

#define HF 264
#define HS_TOTAL_BYTES 69632

// ---------------- CSR build: hist + weight-prep merged -------------------------
__global__ void k_histprep(const int* __restrict__ ei, int E,
                           const float* __restrict__ W1,
                           const float* __restrict__ W3,
                           const float* __restrict__ fc1w) {
    int i = blockIdx.x * blockDim.x + threadIdx.x;

    if (i < 163840) {
        unsigned short h, l;
        if (i < 65536) {
            bsplit(W1[i], h, l);
            ((unsigned short*)g_w1hi)[i] = h;
            ((unsigned short*)g_w1lo)[i] = l;
        } else if (i < 131072) {
            int j = i - 65536;
            bsplit(W3[j], h, l);
            ((unsigned short*)g_w3hi)[j] = h;
            ((unsigned short*)g_w3lo)[j] = l;
        } else {
            int j = i - 131072;
            bsplit(fc1w[j], h, l);
            ((unsigned short*)g_fc1hi)[j] = h;
            ((unsigned short*)g_fc1lo)[j] = l;
        }
    }

    int b = i * 4;
    if (b + 3 < E) {
        int4 d = *reinterpret_cast<const int4*>(ei + E + b);
        atomicAdd(&g_cnt[d.x], 1);
        atomicAdd(&g_cnt[d.y], 1);
        atomicAdd(&g_cnt[d.z], 1);
        atomicAdd(&g_cnt[d.w], 1);
    } else {
        for (int j = b; j < E; j++) atomicAdd(&g_cnt[ei[E + j]], 1);
    }
}

__global__ void __launch_bounds__(1024) k_scan(int n) {
    __shared__ int tmp[1024];
    int tid = threadIdx.x;
    int chunk = (n + 1023) >> 10;
    chunk = (chunk + 3) & ~3;
    int start = tid * chunk;
    int end = start + chunk; if (end > n) end = n;

    int s = 0;
    int i = start;
    for (; i + 3 < end; i += 4) {
        int4 v = *reinterpret_cast<const int4*>(g_cnt + i);
        s += v.x + v.y + v.z + v.w;
    }
    for (; i < end; i++) s += g_cnt[i];
    tmp[tid] = s;
    __syncthreads();
    for (int off = 1; off < 1024; off <<= 1) {
        int v = (tid >= off) ? tmp[tid - off] : 0;
        __syncthreads();
        tmp[tid] += v;
        __syncthreads();
    }
    int base = tmp[tid] - s;
    i = start;
    for (; i + 3 < end; i += 4) {
        int4 v = *reinterpret_cast<const int4*>(g_cnt + i);
        int c0 = v.x, c1 = v.y, c2 = v.z, c3 = v.w;
        g_off[i] = base;     g_pos[i] = base;     g_dinv[i] = rsqrtf((float)(c0 + 1));     base += c0;
        g_off[i + 1] = base; g_pos[i + 1] = base; g_dinv[i + 1] = rsqrtf((float)(c1 + 1)); base += c1;
        g_off[i + 2] = base; g_pos[i + 2] = base; g_dinv[i + 2] = rsqrtf((float)(c2 + 1)); base += c2;
        g_off[i + 3] = base; g_pos[i + 3] = base; g_dinv[i + 3] = rsqrtf((float)(c3 + 1)); base += c3;
    }
    for (; i < end; i++) {
        int c = g_cnt[i];
        g_off[i] = base; g_pos[i] = base;
        g_dinv[i] = rsqrtf((float)(c + 1));
        base += c;
    }
}
__global__ void k_scatter(const int* __restrict__ ei, int E) {
    int i = blockIdx.x * blockDim.x + threadIdx.x;
    int b = i * 4;
    if (b + 3 < E) {
        int4 s = *reinterpret_cast<const int4*>(ei + b);
        int4 d = *reinterpret_cast<const int4*>(ei + E + b);
        g_srt[atomicAdd(&g_pos[d.x], 1)] = s.x;
        g_srt[atomicAdd(&g_pos[d.y], 1)] = s.y;
        g_srt[atomicAdd(&g_pos[d.z], 1)] = s.z;
        g_srt[atomicAdd(&g_pos[d.w], 1)] = s.w;
    } else {
        for (int j = b; j < E; j++)
            g_srt[atomicAdd(&g_pos[ei[E + j]], 1)] = ei[j];
    }
}

// ---------------- standalone pull (high occupancy; warp per node) --------------
__global__ void __launch_bounds__(256) k_pull(const float* __restrict__ in,
                                              float* __restrict__ outbuf, int n) {
    int node = (blockIdx.x * blockDim.x + threadIdx.x) >> 5;
    int lane = threadIdx.x & 31;
    if (node >= n) return;
    int off = g_off[node], cnt = g_cnt[node];
    float dd = g_dinv[node];

    float4 v = reinterpret_cast<const float4*>(in + (size_t)node * 128)[lane];
    float4 acc;
    acc.x = dd * v.x; acc.y = dd * v.y; acc.z = dd * v.z; acc.w = dd * v.w;

    int j = 0;
    for (; j + 7 < cnt; j += 8) {
        int s0 = g_srt[off + j],     s1 = g_srt[off + j + 1];
        int s2 = g_srt[off + j + 2], s3 = g_srt[off + j + 3];
        int s4 = g_srt[off + j + 4], s5 = g_srt[off + j + 5];
        int s6 = g_srt[off + j + 6], s7 = g_srt[off + j + 7];
        float w0 = g_dinv[s0], w1 = g_dinv[s1], w2 = g_dinv[s2], w3 = g_dinv[s3];
        float w4 = g_dinv[s4], w5 = g_dinv[s5], w6 = g_dinv[s6], w7 = g_dinv[s7];
        float4 a0 = reinterpret_cast<const float4*>(in + (size_t)s0 * 128)[lane];
        float4 a1 = reinterpret_cast<const float4*>(in + (size_t)s1 * 128)[lane];
        float4 a2 = reinterpret_cast<const float4*>(in + (size_t)s2 * 128)[lane];
        float4 a3 = reinterpret_cast<const float4*>(in + (size_t)s3 * 128)[lane];
        float4 a4 = reinterpret_cast<const float4*>(in + (size_t)s4 * 128)[lane];
        float4 a5 = reinterpret_cast<const float4*>(in + (size_t)s5 * 128)[lane];
        float4 a6 = reinterpret_cast<const float4*>(in + (size_t)s6 * 128)[lane];
        float4 a7 = reinterpret_cast<const float4*>(in + (size_t)s7 * 128)[lane];
        acc.x += w0 * a0.x + w1 * a1.x + w2 * a2.x + w3 * a3.x
               + w4 * a4.x + w5 * a5.x + w6 * a6.x + w7 * a7.x;
        acc.y += w0 * a0.y + w1 * a1.y + w2 * a2.y + w3 * a3.y
               + w4 * a4.y + w5 * a5.y + w6 * a6.y + w7 * a7.y;
        acc.z += w0 * a0.z + w1 * a1.z + w2 * a2.z + w3 * a3.z
               + w4 * a4.z + w5 * a5.z + w6 * a6.z + w7 * a7.z;
        acc.w += w0 * a0.w + w1 * a1.w + w2 * a2.w + w3 * a3.w
               + w4 * a4.w + w5 * a5.w + w6 * a6.w + w7 * a7.w;
    }
    for (; j < cnt; j++) {
        int s0 = g_srt[off + j];
        float w0 = g_dinv[s0];
        float4 a = reinterpret_cast<const float4*>(in + (size_t)s0 * 128)[lane];
        acc.x += w0 * a.x; acc.y += w0 * a.y; acc.z += w0 * a.z; acc.w += w0 * a.w;
    }
    acc.x *= dd; acc.y *= dd; acc.z *= dd; acc.w *= dd;
    reinterpret_cast<float4*>(outbuf + (size_t)node * 128)[lane] = acc;
}

// ---------------- fused GEMM: T2 = (leaky(A1@W1+b1)) @ W3 (R14-proven) ---------
// grid (MT); block 256 = 8 warps (4m x 2n); reads g_buf1, writes g_buf2
__global__ void __launch_bounds__(256) k_wgemm12(const float* __restrict__ b1, int n) {
    extern __shared__ __nv_bfloat16 sh[];
    __nv_bfloat16* s_ahi = sh + O_AHI;
    __nv_bfloat16* s_alo = sh + O_ALO;
    __nv_bfloat16* s_bhi = sh + O_BHI;
    __nv_bfloat16* s_blo = sh + O_BLO;
    __nv_bfloat16* s_hhi = sh + O_HHI;
    __nv_bfloat16* s_hlo = sh + O_HLO;
    float* stg = reinterpret_cast<float*>(sh + O_BHI);   // fp32 staging [128][SF]

    int tid = threadIdx.x;
    int wid = tid >> 5;
    int base = blockIdx.x * 128;
    int wm = wid & 3;
    int wn = wid >> 2;

    for (int it = tid; it < 128 * 32; it += 256) {
        int r = it >> 5, c4 = (it & 31) << 2;
        float4 v = make_float4(0.f, 0.f, 0.f, 0.f);
        if (base + r < n)
            v = reinterpret_cast<const float4*>(g_buf1 + (size_t)(base + r) * 128)[it & 31];
        ushort4 h, l;
        bsplit(v.x, h.x, l.x); bsplit(v.y, h.y, l.y);
        bsplit(v.z, h.z, l.z); bsplit(v.w, h.w, l.w);
        *reinterpret_cast<ushort4*>(s_ahi + r * SB + c4) = h;
        *reinterpret_cast<ushort4*>(s_alo + r * SB + c4) = l;
    }

    wmma::fragment<wmma::accumulator, 16, 16, 16, float> acc2[2][4];
#pragma unroll
    for (int mi = 0; mi < 2; mi++)
#pragma unroll
        for (int j = 0; j < 4; j++) wmma::fill_fragment(acc2[mi][j], 0.f);

    for (int c = 0; c < 4; c++) {
        for (int it = tid; it < 128 * 16; it += 256) {
            int r = it >> 4, c8 = (it & 15) << 3;
            *reinterpret_cast<uint4*>(s_bhi + r * SB + c8) =
                *reinterpret_cast<const uint4*>(g_w1hi + r * 512 + c * 128 + c8);
            *reinterpret_cast<uint4*>(s_blo + r * SB + c8) =
                *reinterpret_cast<const uint4*>(g_w1lo + r * 512 + c * 128 + c8);
        }
        __syncthreads();

        wmma::fragment<wmma::accumulator, 16, 16, 16, float> acc1[2][4];
#pragma unroll
        for (int mi = 0; mi < 2; mi++)
#pragma unroll
            for (int j = 0; j < 4; j++) wmma::fill_fragment(acc1[mi][j], 0.f);

#pragma unroll
        for (int ks = 0; ks < 8; ks++) {
            wmma::fragment<wmma::matrix_a, 16, 16, 16, __nv_bfloat16, wmma::row_major> ahi[2], alo[2];
#pragma unroll
            for (int mi = 0; mi < 2; mi++) {
                wmma::load_matrix_sync(ahi[mi], s_ahi + (wm * 32 + mi * 16) * SB + ks * 16, SB);
                wmma::load_matrix_sync(alo[mi], s_alo + (wm * 32 + mi * 16) * SB + ks * 16, SB);
            }
#pragma unroll
            for (int j = 0; j < 4; j++) {
                wmma::fragment<wmma::matrix_b, 16, 16, 16, __nv_bfloat16, wmma::row_major> bhi, blo;
                int col = wn * 64 + j * 16;
                wmma::load_matrix_sync(bhi, s_bhi + (ks * 16) * SB + col, SB);
                wmma::load_matrix_sync(blo, s_blo + (ks * 16) * SB + col, SB);
#pragma unroll
                for (int mi = 0; mi < 2; mi++) {
                    wmma::mma_sync(acc1[mi][j], ahi[mi], bhi, acc1[mi][j]);
                    wmma::mma_sync(acc1[mi][j], alo[mi], bhi, acc1[mi][j]);
                    wmma::mma_sync(acc1[mi][j], ahi[mi], blo, acc1[mi][j]);
                }
            }
        }
        __syncthreads();

#pragma unroll
        for (int mi = 0; mi < 2; mi++)
#pragma unroll
            for (int j = 0; j < 4; j++)
                wmma::store_matrix_sync(stg + (wm * 32 + mi * 16) * SF + wn * 64 + j * 16,
                                        acc1[mi][j], SF, wmma::mem_row_major);
        __syncthreads();

        for (int it = tid; it < 128 * 32; it += 256) {
            int r = it >> 5, c4 = (it & 31) << 2;
            float4 v = *reinterpret_cast<float4*>(stg + r * SF + c4);
            float4 bb = *reinterpret_cast<const float4*>(b1 + c * 128 + c4);
            v.x = leaky(v.x + bb.x); v.y = leaky(v.y + bb.y);
            v.z = leaky(v.z + bb.z); v.w = leaky(v.w + bb.w);
            ushort4 h, l;
            bsplit(v.x, h.x, l.x); bsplit(v.y, h.y, l.y);
            bsplit(v.z, h.z, l.z); bsplit(v.w, h.w, l.w);
            *reinterpret_cast<ushort4*>(s_hhi + r * SB + c4) = h;
            *reinterpret_cast<ushort4*>(s_hlo + r * SB + c4) = l;
        }
        __syncthreads();

        for (int it = tid; it < 128 * 16; it += 256) {
            int r = it >> 4, c8 = (it & 15) << 3;
            *reinterpret_cast<uint4*>(s_bhi + r * SB + c8) =
                *reinterpret_cast<const uint4*>(g_w3hi + (c * 128 + r) * 128 + c8);
            *reinterpret_cast<uint4*>(s_blo + r * SB + c8) =
                *reinterpret_cast<const uint4*>(g_w3lo + (c * 128 + r) * 128 + c8);
        }
        __syncthreads();

#pragma unroll
        for (int ks = 0; ks < 8; ks++) {
            wmma::fragment<wmma::matrix_a, 16, 16, 16, __nv_bfloat16, wmma::row_major> ahi[2], alo[2];
#pragma unroll
            for (int mi = 0; mi < 2; mi++) {
                wmma::load_matrix_sync(ahi[mi], s_hhi + (wm * 32 + mi * 16) * SB + ks * 16, SB);
                wmma::load_matrix_sync(alo[mi], s_hlo + (wm * 32 + mi * 16) * SB + ks * 16, SB);
            }
#pragma unroll
            for (int j = 0; j < 4; j++) {
                wmma::fragment<wmma::matrix_b, 16, 16, 16, __nv_bfloat16, wmma::row_major> bhi, blo;
                int col = wn * 64 + j * 16;
                wmma::load_matrix_sync(bhi, s_bhi + (ks * 16) * SB + col, SB);
                wmma::load_matrix_sync(blo, s_blo + (ks * 16) * SB + col, SB);
#pragma unroll
                for (int mi = 0; mi < 2; mi++) {
                    wmma::mma_sync(acc2[mi][j], ahi[mi], bhi, acc2[mi][j]);
                    wmma::mma_sync(acc2[mi][j], alo[mi], bhi, acc2[mi][j]);
                    wmma::mma_sync(acc2[mi][j], ahi[mi], blo, acc2[mi][j]);
                }
            }
        }
        __syncthreads();
    }

#pragma unroll
    for (int mi = 0; mi < 2; mi++)
#pragma unroll
        for (int j = 0; j < 4; j++)
            wmma::store_matrix_sync(stg + (wm * 32 + mi * 16) * SF + wn * 64 + j * 16,
                                    acc2[mi][j], SF, wmma::mem_row_major);
    __syncthreads();

    for (int it = tid; it < 128 * 32; it += 256) {
        int r = it >> 5, c4 = (it & 31) << 2;
        if (base + r >= n) continue;
        float4 v = *reinterpret_cast<float4*>(stg + r * SF + c4);
        *reinterpret_cast<float4*>(g_buf2 + (size_t)(base + r) * 128 + c4) = v;
    }
}

// ---------------- gather-free head (R10-proven): reads g_buf1 ------------------
// grid ceil(n/64); block 256 = 8 warps (2m x 4n)
__global__ void __launch_bounds__(256) k_final(
    const float* __restrict__ b3, const float* __restrict__ fc1b,
    const float* __restrict__ fc2w, const float* __restrict__ fc2b,
    float* __restrict__ out, int n) {
    extern __shared__ __nv_bfloat16 sh[];
    __nv_bfloat16* s_ahi = sh;
    __nv_bfloat16* s_alo = sh + 64 * SB;

    int tid = threadIdx.x;
    int wid = tid >> 5;
    int base = blockIdx.x * 64;

    for (int it = tid; it < 64 * 32; it += 256) {
        int r = it >> 5, c4 = (it & 31) << 2;
        float4 v = make_float4(0.f, 0.f, 0.f, 0.f);
        if (base + r < n)
            v = reinterpret_cast<const float4*>(g_buf1 + (size_t)(base + r) * 128)[it & 31];
        float4 bb = *reinterpret_cast<const float4*>(b3 + c4);
        v.x = leaky(v.x + bb.x); v.y = leaky(v.y + bb.y);
        v.z = leaky(v.z + bb.z); v.w = leaky(v.w + bb.w);
        ushort4 h, l;
        bsplit(v.x, h.x, l.x); bsplit(v.y, h.y, l.y);
        bsplit(v.z, h.z, l.z); bsplit(v.w, h.w, l.w);
        *reinterpret_cast<ushort4*>(s_ahi + r * SB + c4) = h;
        *reinterpret_cast<ushort4*>(s_alo + r * SB + c4) = l;
    }
    __syncthreads();

    int wm = wid & 1;
    int wn = wid >> 1;
    wmma::fragment<wmma::accumulator, 16, 16, 16, float> acc[2][4];
#pragma unroll
    for (int mi = 0; mi < 2; mi++)
#pragma unroll
        for (int j = 0; j < 4; j++) wmma::fill_fragment(acc[mi][j], 0.f);

#pragma unroll
    for (int ks = 0; ks < 8; ks++) {
        wmma::fragment<wmma::matrix_a, 16, 16, 16, __nv_bfloat16, wmma::row_major> ahi[2], alo[2];
#pragma unroll
        for (int mi = 0; mi < 2; mi++) {
            wmma::load_matrix_sync(ahi[mi], s_ahi + (wm * 32 + mi * 16) * SB + ks * 16, SB);
            wmma::load_matrix_sync(alo[mi], s_alo + (wm * 32 + mi * 16) * SB + ks * 16, SB);
        }
#pragma unroll
        for (int j = 0; j < 4; j++) {
            int col = wn * 64 + j * 16;
            wmma::fragment<wmma::matrix_b, 16, 16, 16, __nv_bfloat16, wmma::col_major> bhi, blo;
            wmma::load_matrix_sync(bhi, g_fc1hi + (size_t)col * 128 + ks * 16, 128);
            wmma::load_matrix_sync(blo, g_fc1lo + (size_t)col * 128 + ks * 16, 128);
#pragma unroll
            for (int mi = 0; mi < 2; mi++) {
                wmma::mma_sync(acc[mi][j], ahi[mi], bhi, acc[mi][j]);
                wmma::mma_sync(acc[mi][j], alo[mi], bhi, acc[mi][j]);
                wmma::mma_sync(acc[mi][j], ahi[mi], blo, acc[mi][j]);
            }
        }
    }
    __syncthreads();

    float* e = reinterpret_cast<float*>(sh);
#pragma unroll
    for (int mi = 0; mi < 2; mi++)
#pragma unroll
        for (int j = 0; j < 4; j++)
            wmma::store_matrix_sync(e + (wm * 32 + mi * 16) * HF + wn * 64 + j * 16,
                                    acc[mi][j], HF, wmma::mem_row_major);
    __syncthreads();

    {
        int node = tid >> 2;
        int part = tid & 3;
        float s = 0.f;
        const float* er = e + node * HF + part * 64;
#pragma unroll
        for (int c4 = 0; c4 < 16; c4++) {
            float4 v = *reinterpret_cast<const float4*>(er + c4 * 4);
            float4 fb = *reinterpret_cast<const float4*>(fc1b + part * 64 + c4 * 4);
            float4 w2 = *reinterpret_cast<const float4*>(fc2w + part * 64 + c4 * 4);
            s += leaky(v.x + fb.x) * w2.x + leaky(v.y + fb.y) * w2.y
               + leaky(v.z + fb.z) * w2.z + leaky(v.w + fb.w) * w2.w;
        }
        s += __shfl_xor_sync(0xffffffffu, s, 1);
        s += __shfl_xor_sync(0xffffffffu, s, 2);
        if (part == 0 && base + node < n)
            out[base + node] = s + fc2b[0];
    }
}

// ---------------------------------------------------------------------------
extern "C" void kernel_launch(void* const* d_in, const int* in_sizes, int n_in,
                              void* d_out, int out_size) {
    const float* x    = (const float*)d_in[0];
    const int*   ei   = (const int*)d_in[1];   // int32 (JAX x64 disabled)
    const float* W1   = (const float*)d_in[2];
    const float* b1   = (const float*)d_in[3];
    const float* W3   = (const float*)d_in[4];
    const float* b3   = (const float*)d_in[5];
    const float* fc1w = (const float*)d_in[6];
    const float* fc1b = (const float*)d_in[7];
    const float* fc2w = (const float*)d_in[8];
    const float* fc2b = (const float*)d_in[9];
    float* out = (float*)d_out;

    int n = in_sizes[0] / 128;
    int E = in_sizes[1] / 2;
    int mt = (n + 127) / 128;
    int mt64 = (n + 63) / 64;

    static int smem_set = 0;
    static void* cnt_ptr = nullptr;
    static float* buf1 = nullptr;
    static float* buf2 = nullptr;
    if (!smem_set) {
        cudaFuncSetAttribute(k_wgemm12, cudaFuncAttributeMaxDynamicSharedMemorySize,
                             WG_TOTAL_BYTES);
        cudaFuncSetAttribute(k_final, cudaFuncAttributeMaxDynamicSharedMemorySize,
                             HS_TOTAL_BYTES);
        cudaGetSymbolAddress(&cnt_ptr, g_cnt);
        cudaGetSymbolAddress((void**)&buf1, g_buf1);
        cudaGetSymbolAddress((void**)&buf2, g_buf2);
        smem_set = 1;
    }

    // CSR build
    cudaMemsetAsync(cnt_ptr, 0, (size_t)n * sizeof(int), 0);
    k_histprep<<<(E / 4 + 255) / 256, 256>>>(ei, E, W1, W3, fc1w);  // launch 0
    k_scan<<<1, 1024>>>(n);                                         // launch 1
    k_scatter<<<(E / 4 + 255) / 256, 256>>>(ei, E);                 // launch 2

    // A1 = Ahat @ x -> g_buf1 (high-occupancy standalone)          // launch 3 (profiled)
    k_pull<<<(n * 32 + 255) / 256, 256>>>(x, buf1, n);
    // T2 = leaky(A1@W1+b1) @ W3 -> g_buf2
    k_wgemm12<<<mt, 256, WG_TOTAL_BYTES>>>(b1, n);
    // A2 = Ahat @ T2 -> g_buf1 (high-occupancy standalone)
    k_pull<<<(n * 32 + 255) / 256, 256>>>(buf2, buf1, n);
    // head (gather-free)
    k_final<<<mt64, 256, HS_TOTAL_BYTES>>>(b3, fc1b, fc2w, fc2b, out, n);
}